// round 17
// baseline (speedup 1.0000x reference)
#include <cuda_runtime.h>
#include <math.h>
#include <stdint.h>

#define CB 8
#define CSEQ 2048
#define CT 2049
#define CV 4096
#define CD 1024
#define CH 16
#define CDH 64
#define CNL 8
#define CFF 4096
#define CM (CB*CT)
#define MPAD 16512

__device__ __forceinline__ uint32_t smem_u32(const void* p) {
    uint32_t a;
    asm("{ .reg .u64 t; cvta.to.shared.u64 t, %1; cvt.u32.u64 %0, t; }" : "=r"(a) : "l"(p));
    return a;
}
#define CP_COMMIT() asm volatile("cp.async.commit_group;" ::: "memory")
#define CP_WAIT1()  asm volatile("cp.async.wait_group 1;" ::: "memory")
#define CP_WAIT0()  asm volatile("cp.async.wait_group 0;" ::: "memory")

__device__ __forceinline__ void ldgsts(uint32_t dst, const void* src) {
    asm volatile("cp.async.cg.shared.global [%0], [%1], 16;" :: "r"(dst), "l"(src) : "memory");
}
__device__ __forceinline__ void ldm4(uint32_t* r, uint32_t addr) {
    asm volatile("ldmatrix.sync.aligned.m8n8.x4.shared.b16 {%0,%1,%2,%3}, [%4];"
        : "=r"(r[0]), "=r"(r[1]), "=r"(r[2]), "=r"(r[3]) : "r"(addr));
}
// s8 IMMA: m16n8k32, s32 accum
__device__ __forceinline__ void mma_s8(int* c, const uint32_t* a, uint32_t b0, uint32_t b1) {
    asm volatile("mma.sync.aligned.m16n8k32.row.col.s32.s8.s8.s32 "
        "{%0,%1,%2,%3}, {%4,%5,%6,%7}, {%8,%9}, {%0,%1,%2,%3};"
        : "+r"(c[0]), "+r"(c[1]), "+r"(c[2]), "+r"(c[3])
        : "r"(a[0]), "r"(a[1]), "r"(a[2]), "r"(a[3]), "r"(b0), "r"(b1));
}

// weight int8 offsets (elements)
#define W_TOTAL 104857600ull
#define W_WE    0ull
#define W_L(l)  (4194304ull + (unsigned long long)(l)*12582912ull)
#define W_Q(l)  (W_L(l))
#define W_K(l)  (W_L(l) + 1048576ull)
#define W_V(l)  (W_L(l) + 2097152ull)
#define W_O(l)  (W_L(l) + 3145728ull)
#define W_W1(l) (W_L(l) + 4194304ull)
#define W_W2(l) (W_L(l) + 8388608ull)
// weight scale offsets
#define NSC 74752
#define SC_WE 0
#define SC_L(l) (1024 + (l)*9216)
#define SC_Q(l)  (SC_L(l))
#define SC_K(l)  (SC_L(l)+1024)
#define SC_V(l)  (SC_L(l)+2048)
#define SC_O(l)  (SC_L(l)+3072)
#define SC_W1(l) (SC_L(l)+4096)
#define SC_W2(l) (SC_L(l)+8192)

__device__ __align__(16) char g_wb1[W_TOTAL];
__device__ __align__(16) char g_wb2[W_TOTAL];
__device__ float g_sbw[NSC];
__device__ float g_winv[NSC];

__device__ __align__(16) char g_ia1[(size_t)16384*CV];
__device__ __align__(16) char g_ia2[(size_t)16384*CV];
__device__ float g_isa[16384];
__device__ __align__(16) char g_xa1[(size_t)MPAD*CD];
__device__ __align__(16) char g_xa2[(size_t)MPAD*CD];
__device__ float g_xsa[MPAD];
__device__ __align__(16) char g_qa1[(size_t)MPAD*CD];
__device__ __align__(16) char g_qa2[(size_t)MPAD*CD];
__device__ float g_qsa[MPAD];
__device__ __align__(16) char g_fa1[(size_t)MPAD*CFF];
__device__ __align__(16) char g_fa2[(size_t)MPAD*CFF];
__device__ float g_fsa[MPAD];

__device__ float g_x  [(size_t)CM*CD];
__device__ float g_q  [(size_t)CM*CD];
__device__ float g_k  [(size_t)CM*CD];
__device__ float g_v  [(size_t)CM*CD];
__device__ float g_tmp[(size_t)CM*CD];
__device__ float g_ff [(size_t)CM*CFF];
__device__ float g_kvp [(size_t)CB*CH*8*CDH*CDH];
__device__ float g_ksp [(size_t)CB*CH*8*CDH];
__device__ float g_kv  [(size_t)CB*CH*CDH*CDH];
__device__ float g_ksum[(size_t)CB*CH*CDH];
__device__ float g_cls [(size_t)CB*CD];

__device__ __forceinline__ float geluf(float v) {
    return 0.5f * v * (1.0f + erff(v * 0.70710678118654752f));
}

// ---------------- weight preprocessing ----------------
// column-wise absmax of W[K,N] -> per-output-row scales
__global__ void w_colmax(const float* __restrict__ W, float* __restrict__ sbw,
                         float* __restrict__ winv, int K, int N)
{
    int n = blockIdx.x * 256 + threadIdx.x;
    if (n >= N) return;
    float m = 1e-30f;
    for (int k = 0; k < K; k++)
        m = fmaxf(m, fabsf(W[(size_t)k * N + n]));
    sbw[n] = m * (1.0f / 127.0f);
    winv[n] = 127.0f / m;
}

// W[K,N] fp32 -> transposed int8 pair [N,K]
__global__ __launch_bounds__(256) void w_quant(const float* __restrict__ W,
                                               const float* __restrict__ winv,
                                               char* __restrict__ B1, char* __restrict__ B2,
                                               int K, int N)
{
    __shared__ float tile[32][33];
    int kb = blockIdx.y * 32, nb = blockIdx.x * 32;
    int tx = threadIdx.x & 31, ty = threadIdx.x >> 5;
    for (int i = ty; i < 32; i += 8)
        tile[i][tx] = W[(size_t)(kb + i) * N + nb + tx];
    __syncthreads();
    for (int i = ty; i < 32; i += 8) {
        float inv = winv[nb + i];
        float f = tile[tx][i] * inv;
        int q1 = __float2int_rn(f);
        int q2 = __float2int_rn((f - (float)q1) * 252.0f);
        size_t o = (size_t)(nb + i) * K + kb + tx;
        B1[o] = (char)q1;
        B2[o] = (char)q2;
    }
}

// ---------------- row quantizer: fp32 [rows,K] -> int8 pair + per-row scale ----------------
__global__ __launch_bounds__(256) void quant_rows(const float* __restrict__ src,
                                                  char* __restrict__ a1, char* __restrict__ a2,
                                                  float* __restrict__ sa, int K)
{
    int row = blockIdx.x;
    int t = threadIdx.x;
    size_t base = (size_t)row * K;
    float m = 0.f;
    for (int c = t * 4; c < K; c += 1024) {
        float4 v = *(const float4*)(src + base + c);
        m = fmaxf(m, fmaxf(fmaxf(fabsf(v.x), fabsf(v.y)), fmaxf(fabsf(v.z), fabsf(v.w))));
    }
#pragma unroll
    for (int o = 16; o > 0; o >>= 1)
        m = fmaxf(m, __shfl_xor_sync(0xffffffffu, m, o));
    __shared__ float sm_[9];
    int w = t >> 5;
    if ((t & 31) == 0) sm_[w] = m;
    __syncthreads();
    if (t == 0) {
        float M = sm_[0];
        for (int i = 1; i < 8; i++) M = fmaxf(M, sm_[i]);
        float s = fmaxf(M, 1e-30f);
        sm_[8] = 127.0f / s;
        sa[row] = s * (1.0f / 127.0f);
    }
    __syncthreads();
    float inv = sm_[8];
    for (int c = t * 4; c < K; c += 1024) {
        float4 v = *(const float4*)(src + base + c);
        float f0 = v.x * inv, f1 = v.y * inv, f2 = v.z * inv, f3 = v.w * inv;
        int i0 = __float2int_rn(f0), i1 = __float2int_rn(f1);
        int i2 = __float2int_rn(f2), i3 = __float2int_rn(f3);
        char4 q1 = make_char4((char)i0, (char)i1, (char)i2, (char)i3);
        char4 q2 = make_char4((char)__float2int_rn((f0 - i0) * 252.0f),
                              (char)__float2int_rn((f1 - i1) * 252.0f),
                              (char)__float2int_rn((f2 - i2) * 252.0f),
                              (char)__float2int_rn((f3 - i3) * 252.0f));
        *(char4*)(a1 + base + c) = q1;
        *(char4*)(a2 + base + c) = q2;
    }
}

// ---------------- int8 split GEMM: C[M,N] = A[M,K] @ B[N,K]^T ----------------
// CTA 128x128, chunk = 64 bytes of K, 2-stage cp.async (R12 structure).
// Stage: A1 8K | A2 8K | B1 8K | B2 8K = 32KB.
#define TG_SMEM 65536
#define STG 32768
template<int EPI>
__global__ __launch_bounds__(256, 1) void tgemm(
    const char* __restrict__ A1, const char* __restrict__ A2, const float* __restrict__ sa,
    const char* __restrict__ B1, const char* __restrict__ B2, const float* __restrict__ sbw,
    const float* __restrict__ bias, const float* __restrict__ pos,
    float* __restrict__ outf, int M, int N, int K)
{
    extern __shared__ char smem[];
    const uint32_t sbase = smem_u32(smem);
    const int tid = threadIdx.x;
    const int lane = tid & 31, wid = tid >> 5;
    const int wm = wid >> 2, wn = wid & 3;           // 2(M) x 4(N); warp tile 64x32
    const int rowBase = blockIdx.y * 128;
    const int colBase = blockIdx.x * 128;
    const int NC = K >> 6;

    int c0[4][4][4], c1[4][4][4];
#pragma unroll
    for (int i = 0; i < 4; i++)
#pragma unroll
        for (int j = 0; j < 4; j++)
#pragma unroll
            for (int p = 0; p < 4; p++) { c0[i][j][p] = 0; c1[i][j][p] = 0; }

    // ldmatrix addressing
    const int lr = lane & 15;
    const int hb = (lane >> 4) << 4;
    const uint32_t xorv = (((uint32_t)lr >> 1) & 3) << 4;
    const int brow = (lane & 7) + ((lane >> 4) << 3);
    const int bko = ((lane >> 3) & 1) << 4;
    const uint32_t bxor = (((uint32_t)brow >> 1) & 3) << 4;

    // ---- prologue: chunk 0 -> stage 0 ----
    {
        uint32_t sb = sbase;
#pragma unroll
        for (int it = 0; it < 2; it++) {
            int idx = it * 256 + tid;
            int r = idx >> 2, c4 = idx & 3;
            uint32_t off = (uint32_t)r * 64 + (((uint32_t)c4 << 4) ^ ((((uint32_t)r >> 1) & 3) << 4));
            size_t ao = (size_t)(rowBase + r) * K + c4 * 16;
            size_t bo = (size_t)(colBase + r) * K + c4 * 16;
            ldgsts(sb + off,         A1 + ao);
            ldgsts(sb + 8192 + off,  A2 + ao);
            ldgsts(sb + 16384 + off, B1 + bo);
            ldgsts(sb + 24576 + off, B2 + bo);
        }
        CP_COMMIT();
    }

    for (int ch = 0; ch < NC; ch++) {
        if (ch + 1 < NC) {
            uint32_t sb = sbase + ((ch + 1) & 1) * STG;
            size_t kc = (size_t)(ch + 1) * 64;
#pragma unroll
            for (int it = 0; it < 2; it++) {
                int idx = it * 256 + tid;
                int r = idx >> 2, c4 = idx & 3;
                uint32_t off = (uint32_t)r * 64 + (((uint32_t)c4 << 4) ^ ((((uint32_t)r >> 1) & 3) << 4));
                size_t ao = (size_t)(rowBase + r) * K + kc + c4 * 16;
                size_t bo = (size_t)(colBase + r) * K + kc + c4 * 16;
                ldgsts(sb + off,         A1 + ao);
                ldgsts(sb + 8192 + off,  A2 + ao);
                ldgsts(sb + 16384 + off, B1 + bo);
                ldgsts(sb + 24576 + off, B2 + bo);
            }
            CP_COMMIT();
            CP_WAIT1();
        } else {
            CP_WAIT0();
        }
        __syncthreads();

        uint32_t sb = sbase + (ch & 1) * STG;
#pragma unroll
        for (int kk = 0; kk < 2; kk++) {
            uint32_t cb = ((uint32_t)(kk * 32 + hb)) ^ xorv;
            uint32_t a1f[4][4], a2f[4][4];
#pragma unroll
            for (int mi = 0; mi < 4; mi++) {
                uint32_t ad = sb + (uint32_t)(wm * 64 + mi * 16 + lr) * 64 + cb;
                ldm4(a1f[mi], ad);
                ldm4(a2f[mi], ad + 8192);
            }
#pragma unroll
            for (int j = 0; j < 2; j++) {
                uint32_t b1f[4], b2f[4];
                uint32_t bd = sb + 16384 + (uint32_t)(wn * 32 + j * 16 + brow) * 64
                            + (((uint32_t)(kk * 32 + bko)) ^ bxor);
                ldm4(b1f, bd);
                ldm4(b2f, bd + 8192);
#pragma unroll
                for (int mi = 0; mi < 4; mi++) {
#pragma unroll
                    for (int od = 0; od < 2; od++) {
                        int nj = j * 2 + od;
                        mma_s8(c0[mi][nj], a1f[mi], b1f[od * 2], b1f[od * 2 + 1]);
                        mma_s8(c1[mi][nj], a1f[mi], b2f[od * 2], b2f[od * 2 + 1]);
                        mma_s8(c1[mi][nj], a2f[mi], b1f[od * 2], b1f[od * 2 + 1]);
                    }
                }
            }
        }
        __syncthreads();
    }

    // ---- epilogue: dequant + bias (+gelu / +pos) ----
    const int cr = lane >> 2;
    const int ccol = (lane & 3) * 2;
    const float r252 = 1.0f / 252.0f;
#pragma unroll
    for (int mi = 0; mi < 4; mi++) {
#pragma unroll
        for (int half = 0; half < 2; half++) {
            int row = rowBase + wm * 64 + mi * 16 + cr + half * 8;
            if (row >= M) continue;
            float sav = sa[row];
            size_t orow = (size_t)row;
            const float* prow = nullptr;
            if (EPI == 2) {
                int n = row >> 11, s = row & 2047;
                orow = (size_t)n * CT + s + 1;
                prow = pos + (size_t)(s + 1) * CD;
            }
#pragma unroll
            for (int nj = 0; nj < 4; nj++) {
                int col = colBase + wn * 32 + nj * 8 + ccol;
                float2 sb2 = *(const float2*)&sbw[col];
                float2 bb = *(const float2*)&bias[col];
                int e = half * 2;
                float v0 = sav * sb2.x * ((float)c0[mi][nj][e]     + (float)c1[mi][nj][e]     * r252) + bb.x;
                float v1 = sav * sb2.y * ((float)c0[mi][nj][e + 1] + (float)c1[mi][nj][e + 1] * r252) + bb.y;
                if (EPI == 1) { v0 = geluf(v0); v1 = geluf(v1); }
                if (EPI == 2) { v0 += prow[col]; v1 += prow[col + 1]; }
                float2 o; o.x = v0; o.y = v1;
                *(float2*)&outf[orow * N + col] = o;
            }
        }
    }
}

// ---------------- CLS row ----------------
__global__ void cls_kernel(const float* __restrict__ We, const float* __restrict__ be,
                           const float* __restrict__ pos, float* __restrict__ x)
{
    int idx = blockIdx.x * 256 + threadIdx.x;
    if (idx >= CB * CD) return;
    int n = idx >> 10, c = idx & 1023;
    x[(size_t)n * CT * CD + c] = We[(size_t)(CV - 1) * CD + c] + be[c] + pos[c];
}

// ---------------- RoPE + phi ----------------
__global__ void rope_phi_kernel(float* __restrict__ q, float* __restrict__ k)
{
    int idx = blockIdx.x * 256 + threadIdx.x;
    if (idx >= CB * CT * CH * 32) return;
    int j  = idx & 31;
    int h  = (idx >> 5) & 15;
    int nt = idx >> 9;
    int tt = nt % CT;
    int n  = nt / CT;
    size_t base = (((size_t)n * CT + tt) * CH + h) * CDH;
    float invf = 1.0f / powf(10000.0f, (float)(2 * j) / (float)CDH);
    float ang = (float)tt * invf;
    float c, s;
    sincosf(ang, &s, &c);
    float q1 = q[base + j], q2 = q[base + j + 32];
    float qa = q1 * c - q2 * s, qb = q2 * c + q1 * s;
    q[base + j]      = (qa > 0.f) ? (qa + 1.f) : expf(qa);
    q[base + j + 32] = (qb > 0.f) ? (qb + 1.f) : expf(qb);
    float k1 = k[base + j], k2 = k[base + j + 32];
    float ka = k1 * c - k2 * s, kb = k2 * c + k1 * s;
    k[base + j]      = (ka > 0.f) ? (ka + 1.f) : expf(ka);
    k[base + j + 32] = (kb > 0.f) ? (kb + 1.f) : expf(kb);
}

// ---------------- KV partials ----------------
__global__ __launch_bounds__(256) void kv_partial(const float* __restrict__ Kf, const float* __restrict__ Vf,
                                                  float* __restrict__ kvp, float* __restrict__ ksp)
{
    int nh = blockIdx.x, ch = blockIdx.y;
    int n = nh >> 4, h = nh & 15;
    int s0 = ch * 257, s1 = min(s0 + 257, CT);
    int t = threadIdx.x;
    int d0 = t >> 2, mq = (t & 3) << 4;
    __shared__ float sk[8][64];
    __shared__ float sv[8][64];
    float acc[16];
#pragma unroll
    for (int j = 0; j < 16; j++) acc[j] = 0.f;
    float ks = 0.f;
    for (int s = s0; s < s1; s += 8) {
        int nr = min(8, s1 - s);
        for (int i = t; i < nr * 64; i += 256) {
            int rr = i >> 6, dd = i & 63;
            size_t off = (((size_t)n * CT + (s + rr)) * CH + h) * CDH + dd;
            sk[rr][dd] = Kf[off];
            sv[rr][dd] = Vf[off];
        }
        __syncthreads();
        for (int rr = 0; rr < nr; rr++) {
            float kd = sk[rr][d0];
            ks += kd;
            const float4* v4 = (const float4*)&sv[rr][mq];
            float4 v0 = v4[0], v1 = v4[1], v2 = v4[2], v3 = v4[3];
            acc[0]  += kd * v0.x;  acc[1]  += kd * v0.y;  acc[2]  += kd * v0.z;  acc[3]  += kd * v0.w;
            acc[4]  += kd * v1.x;  acc[5]  += kd * v1.y;  acc[6]  += kd * v1.z;  acc[7]  += kd * v1.w;
            acc[8]  += kd * v2.x;  acc[9]  += kd * v2.y;  acc[10] += kd * v2.z;  acc[11] += kd * v2.w;
            acc[12] += kd * v3.x;  acc[13] += kd * v3.y;  acc[14] += kd * v3.z;  acc[15] += kd * v3.w;
        }
        __syncthreads();
    }
    size_t ob = ((size_t)nh * 8 + ch) * (CDH * CDH) + (size_t)d0 * CDH + mq;
#pragma unroll
    for (int j = 0; j < 16; j++) kvp[ob + j] = acc[j];
    if ((t & 3) == 0) ksp[((size_t)nh * 8 + ch) * CDH + d0] = ks;
}

__global__ void kv_reduce(const float* __restrict__ kvp, const float* __restrict__ ksp,
                          float* __restrict__ kv, float* __restrict__ ksum)
{
    int idx = blockIdx.x * 256 + threadIdx.x;
    const int NKV = CB * CH * CDH * CDH;
    if (idx < NKV) {
        int nh = idx >> 12, r = idx & 4095;
        float s = 0.f;
        for (int c = 0; c < 8; c++) s += kvp[((size_t)nh * 8 + c) * (CDH * CDH) + r];
        kv[idx] = s;
    } else if (idx < NKV + CB * CH * CDH) {
        int i2 = idx - NKV;
        int nh = i2 >> 6, r = i2 & 63;
        float s = 0.f;
        for (int c = 0; c < 8; c++) s += ksp[((size_t)nh * 8 + c) * CDH + r];
        ksum[i2] = s;
    }
}

// ---------------- attn (fp32 out, in place into q) ----------------
__global__ __launch_bounds__(256) void attn_kernel(const float* __restrict__ Qf, const float* __restrict__ kv,
                                                   const float* __restrict__ ksum, float* __restrict__ outf)
{
    int nh = blockIdx.x, ch = blockIdx.y;
    int n = nh >> 4, h = nh & 15;
    int t = threadIdx.x;
    __shared__ float skvt[64][68];
    __shared__ float sks[64];
    __shared__ float sq[4][64];
    for (int i = t; i < 4096; i += 256) {
        int d = i >> 6, m = i & 63;
        skvt[m][d] = kv[(size_t)nh * 4096 + i];
    }
    if (t < 64) sks[t] = ksum[(size_t)nh * 64 + t];
    __syncthreads();
    int g = t >> 6, m = t & 63;
    int s0 = ch * 257, s1 = min(s0 + 257, CT);
    for (int tt = s0; tt < s1; tt += 4) {
        int nr = min(4, s1 - tt);
        if (t < nr * 64)
            sq[t >> 6][t & 63] = Qf[(((size_t)n * CT + (tt + (t >> 6))) * CH + h) * CDH + (t & 63)];
        __syncthreads();
        if (g < nr) {
            float sm = 0.f, sz = 0.f;
#pragma unroll
            for (int d = 0; d < 64; d += 4) {
                float4 q4 = *(const float4*)&sq[g][d];
                float4 k4 = *(const float4*)&skvt[m][d];
                float4 z4 = *(const float4*)&sks[d];
                sm += q4.x * k4.x + q4.y * k4.y + q4.z * k4.z + q4.w * k4.w;
                sz += q4.x * z4.x + q4.y * z4.y + q4.z * z4.z + q4.w * z4.w;
            }
            outf[(((size_t)n * CT + (tt + g)) * CH + h) * CDH + m] = sm / (sz + 1e-6f);
        }
        __syncthreads();
    }
}

// ---------------- residual + LN (in place) + fused row quantization ----------------
__global__ __launch_bounds__(256) void ln_quant(float* __restrict__ x, const float* __restrict__ res,
                                                const float* __restrict__ g, const float* __restrict__ b,
                                                char* __restrict__ a1, char* __restrict__ a2,
                                                float* __restrict__ sa)
{
    int row = blockIdx.x;
    int t = threadIdx.x;
    size_t base = (size_t)row * CD + t * 4;
    float4 a = *(const float4*)(x + base);
    float4 r = *(const float4*)(res + base);
    a.x += r.x; a.y += r.y; a.z += r.z; a.w += r.w;
    float s  = a.x + a.y + a.z + a.w;
    float ss = a.x * a.x + a.y * a.y + a.z * a.z + a.w * a.w;
#pragma unroll
    for (int o = 16; o > 0; o >>= 1) {
        s  += __shfl_xor_sync(0xffffffffu, s,  o);
        ss += __shfl_xor_sync(0xffffffffu, ss, o);
    }
    __shared__ float sh[28];
    int w = t >> 5;
    if ((t & 31) == 0) { sh[w] = s; sh[8 + w] = ss; }
    __syncthreads();
    if (t == 0) {
        float S = 0.f, SS = 0.f;
        for (int i = 0; i < 8; i++) { S += sh[i]; SS += sh[8 + i]; }
        float m = S * (1.f / CD);
        sh[16] = m;
        sh[17] = rsqrtf(SS * (1.f / CD) - m * m + 1e-5f);
    }
    __syncthreads();
    float m = sh[16], inv = sh[17];
    float4 gg = *(const float4*)(g + t * 4);
    float4 bb = *(const float4*)(b + t * 4);
    float4 o;
    o.x = (a.x - m) * inv * gg.x + bb.x;
    o.y = (a.y - m) * inv * gg.y + bb.y;
    o.z = (a.z - m) * inv * gg.z + bb.z;
    o.w = (a.w - m) * inv * gg.w + bb.w;
    *(float4*)(x + base) = o;

    // row absmax -> int8 pair
    float mx = fmaxf(fmaxf(fabsf(o.x), fabsf(o.y)), fmaxf(fabsf(o.z), fabsf(o.w)));
#pragma unroll
    for (int of = 16; of > 0; of >>= 1)
        mx = fmaxf(mx, __shfl_xor_sync(0xffffffffu, mx, of));
    if ((t & 31) == 0) sh[18 + w] = mx;
    __syncthreads();
    if (t == 0) {
        float M = sh[18];
        for (int i = 1; i < 8; i++) M = fmaxf(M, sh[18 + i]);
        float sc = fmaxf(M, 1e-30f);
        sh[26] = 127.0f / sc;
        sa[row] = sc * (1.0f / 127.0f);
    }
    __syncthreads();
    float qi = sh[26];
    float f0 = o.x * qi, f1 = o.y * qi, f2 = o.z * qi, f3 = o.w * qi;
    int i0 = __float2int_rn(f0), i1 = __float2int_rn(f1);
    int i2 = __float2int_rn(f2), i3 = __float2int_rn(f3);
    *(char4*)(a1 + base) = make_char4((char)i0, (char)i1, (char)i2, (char)i3);
    *(char4*)(a2 + base) = make_char4((char)__float2int_rn((f0 - i0) * 252.0f),
                                      (char)__float2int_rn((f1 - i1) * 252.0f),
                                      (char)__float2int_rn((f2 - i2) * 252.0f),
                                      (char)__float2int_rn((f3 - i3) * 252.0f));
}

// ---------------- final LN on CLS rows ----------------
__global__ __launch_bounds__(256) void ln_cls_kernel(const float* __restrict__ x, const float* __restrict__ g,
                                                     const float* __restrict__ b, float* __restrict__ outp)
{
    int n = blockIdx.x;
    int t = threadIdx.x;
    size_t base = (size_t)n * CT * CD + t * 4;
    float4 a = *(const float4*)(x + base);
    float s  = a.x + a.y + a.z + a.w;
    float ss = a.x * a.x + a.y * a.y + a.z * a.z + a.w * a.w;
#pragma unroll
    for (int o = 16; o > 0; o >>= 1) {
        s  += __shfl_xor_sync(0xffffffffu, s,  o);
        ss += __shfl_xor_sync(0xffffffffu, ss, o);
    }
    __shared__ float sh[18];
    int w = t >> 5;
    if ((t & 31) == 0) { sh[w] = s; sh[8 + w] = ss; }
    __syncthreads();
    if (t == 0) {
        float S = 0.f, SS = 0.f;
        for (int i = 0; i < 8; i++) { S += sh[i]; SS += sh[8 + i]; }
        float m = S * (1.f / CD);
        sh[16] = m;
        sh[17] = rsqrtf(SS * (1.f / CD) - m * m + 1e-5f);
    }
    __syncthreads();
    float m = sh[16], inv = sh[17];
    float4 gg = *(const float4*)(g + t * 4);
    float4 bb = *(const float4*)(b + t * 4);
    float4 o;
    o.x = (a.x - m) * inv * gg.x + bb.x;
    o.y = (a.y - m) * inv * gg.y + bb.y;
    o.z = (a.z - m) * inv * gg.z + bb.z;
    o.w = (a.w - m) * inv * gg.w + bb.w;
    *(float4*)(outp + (size_t)n * CD + t * 4) = o;
}

// ---------------- output head ----------------
__global__ __launch_bounds__(256) void out_kernel(const float* __restrict__ xc, const float* __restrict__ Wout,
                                                  const float* __restrict__ bout, float* __restrict__ out)
{
    int c = blockIdx.x * 256 + threadIdx.x;
    __shared__ float sx[CB][CD];
    for (int i = threadIdx.x; i < CB * CD; i += 256)
        sx[i >> 10][i & 1023] = xc[i];
    __syncthreads();
    float acc[CB];
#pragma unroll
    for (int n = 0; n < CB; n++) acc[n] = bout[c];
    for (int d = 0; d < CD; d++) {
        float wv = Wout[(size_t)d * CV + c];
#pragma unroll
        for (int n = 0; n < CB; n++) acc[n] += sx[n][d] * wv;
    }
#pragma unroll
    for (int n = 0; n < CB; n++) out[(size_t)n * CV + c] = acc[n];
}

// ---------------- host ----------------
extern "C" void kernel_launch(void* const* d_in, const int* in_sizes, int n_in,
                              void* d_out, int out_size)
{
    (void)in_sizes; (void)n_in; (void)out_size;
    const float* inputs = (const float*)d_in[0];
    const float* We   = (const float*)d_in[1];
    const float* be   = (const float*)d_in[2];
    const float* pos  = (const float*)d_in[3];
    const float* Wq   = (const float*)d_in[4];
    const float* bq   = (const float*)d_in[5];
    const float* Wk   = (const float*)d_in[6];
    const float* bk   = (const float*)d_in[7];
    const float* Wv   = (const float*)d_in[8];
    const float* bv   = (const float*)d_in[9];
    const float* Wo   = (const float*)d_in[10];
    const float* bo   = (const float*)d_in[11];
    const float* ln1g = (const float*)d_in[12];
    const float* ln1b = (const float*)d_in[13];
    const float* W1   = (const float*)d_in[14];
    const float* b1   = (const float*)d_in[15];
    const float* W2   = (const float*)d_in[16];
    const float* b2   = (const float*)d_in[17];
    const float* ln2g = (const float*)d_in[18];
    const float* ln2b = (const float*)d_in[19];
    const float* gN   = (const float*)d_in[20];
    const float* bN   = (const float*)d_in[21];
    const float* Wout = (const float*)d_in[22];
    const float* bout = (const float*)d_in[23];
    float* out = (float*)d_out;

    float *x, *q, *k, *v, *tmp, *ff, *kvp, *ksp, *kv, *ksum, *clsb;
    float *sbw, *winv, *isa, *xsa, *qsa, *fsa;
    char *wb1, *wb2, *ia1, *ia2, *xa1, *xa2, *qa1, *qa2, *fa1, *fa2;
    cudaGetSymbolAddress((void**)&x,    g_x);
    cudaGetSymbolAddress((void**)&q,    g_q);
    cudaGetSymbolAddress((void**)&k,    g_k);
    cudaGetSymbolAddress((void**)&v,    g_v);
    cudaGetSymbolAddress((void**)&tmp,  g_tmp);
    cudaGetSymbolAddress((void**)&ff,   g_ff);
    cudaGetSymbolAddress((void**)&kvp,  g_kvp);
    cudaGetSymbolAddress((void**)&ksp,  g_ksp);
    cudaGetSymbolAddress((void**)&kv,   g_kv);
    cudaGetSymbolAddress((void**)&ksum, g_ksum);
    cudaGetSymbolAddress((void**)&clsb, g_cls);
    cudaGetSymbolAddress((void**)&wb1,  g_wb1);
    cudaGetSymbolAddress((void**)&wb2,  g_wb2);
    cudaGetSymbolAddress((void**)&sbw,  g_sbw);
    cudaGetSymbolAddress((void**)&winv, g_winv);
    cudaGetSymbolAddress((void**)&ia1,  g_ia1);
    cudaGetSymbolAddress((void**)&ia2,  g_ia2);
    cudaGetSymbolAddress((void**)&isa,  g_isa);
    cudaGetSymbolAddress((void**)&xa1,  g_xa1);
    cudaGetSymbolAddress((void**)&xa2,  g_xa2);
    cudaGetSymbolAddress((void**)&xsa,  g_xsa);
    cudaGetSymbolAddress((void**)&qa1,  g_qa1);
    cudaGetSymbolAddress((void**)&qa2,  g_qa2);
    cudaGetSymbolAddress((void**)&qsa,  g_qsa);
    cudaGetSymbolAddress((void**)&fa1,  g_fa1);
    cudaGetSymbolAddress((void**)&fa2,  g_fa2);
    cudaGetSymbolAddress((void**)&fsa,  g_fsa);

    cudaFuncSetAttribute(tgemm<0>, cudaFuncAttributeMaxDynamicSharedMemorySize, TG_SMEM);
    cudaFuncSetAttribute(tgemm<1>, cudaFuncAttributeMaxDynamicSharedMemorySize, TG_SMEM);
    cudaFuncSetAttribute(tgemm<2>, cudaFuncAttributeMaxDynamicSharedMemorySize, TG_SMEM);

    // ---- preprocess: quantize inputs + all weights ----
    quant_rows<<<16384, 256>>>(inputs, ia1, ia2, isa, CV);
    w_colmax<<<CD / 256, 256>>>(We, sbw + SC_WE, winv + SC_WE, CV, CD);
    w_quant<<<dim3(CD / 32, CV / 32), 256>>>(We, winv + SC_WE, wb1 + W_WE, wb2 + W_WE, CV, CD);
    for (int l = 0; l < CNL; l++) {
        w_colmax<<<CD / 256, 256>>>(Wq + (size_t)l * CD * CD, sbw + SC_Q(l), winv + SC_Q(l), CD, CD);
        w_quant<<<dim3(CD / 32, CD / 32), 256>>>(Wq + (size_t)l * CD * CD, winv + SC_Q(l), wb1 + W_Q(l), wb2 + W_Q(l), CD, CD);
        w_colmax<<<CD / 256, 256>>>(Wk + (size_t)l * CD * CD, sbw + SC_K(l), winv + SC_K(l), CD, CD);
        w_quant<<<dim3(CD / 32, CD / 32), 256>>>(Wk + (size_t)l * CD * CD, winv + SC_K(l), wb1 + W_K(l), wb2 + W_K(l), CD, CD);
        w_colmax<<<CD / 256, 256>>>(Wv + (size_t)l * CD * CD, sbw + SC_V(l), winv + SC_V(l), CD, CD);
        w_quant<<<dim3(CD / 32, CD / 32), 256>>>(Wv + (size_t)l * CD * CD, winv + SC_V(l), wb1 + W_V(l), wb2 + W_V(l), CD, CD);
        w_colmax<<<CD / 256, 256>>>(Wo + (size_t)l * CD * CD, sbw + SC_O(l), winv + SC_O(l), CD, CD);
        w_quant<<<dim3(CD / 32, CD / 32), 256>>>(Wo + (size_t)l * CD * CD, winv + SC_O(l), wb1 + W_O(l), wb2 + W_O(l), CD, CD);
        w_colmax<<<CFF / 256, 256>>>(W1 + (size_t)l * CD * CFF, sbw + SC_W1(l), winv + SC_W1(l), CD, CFF);
        w_quant<<<dim3(CFF / 32, CD / 32), 256>>>(W1 + (size_t)l * CD * CFF, winv + SC_W1(l), wb1 + W_W1(l), wb2 + W_W1(l), CD, CFF);
        w_colmax<<<CD / 256, 256>>>(W2 + (size_t)l * CFF * CD, sbw + SC_W2(l), winv + SC_W2(l), CFF, CD);
        w_quant<<<dim3(CD / 32, CFF / 32), 256>>>(W2 + (size_t)l * CFF * CD, winv + SC_W2(l), wb1 + W_W2(l), wb2 + W_W2(l), CFF, CD);
    }

    // ---- embedding GEMM -> x (+pos, row remap), then CLS, then quantize x rows ----
    tgemm<2><<<dim3(CD / 128, 128), 256, TG_SMEM>>>(
        ia1, ia2, isa, wb1 + W_WE, wb2 + W_WE, sbw + SC_WE,
        be, pos, x, 16384, CD, CV);
    cls_kernel<<<(CB * CD + 255) / 256, 256>>>(We, be, pos, x);
    quant_rows<<<CM, 256>>>(x, xa1, xa2, xsa, CD);

    const int M = CM;
    dim3 gDD(CD / 128, (M + 127) / 128);
    dim3 gDF(CFF / 128, (M + 127) / 128);

    for (int l = 0; l < CNL; l++) {
        tgemm<0><<<gDD, 256, TG_SMEM>>>(xa1, xa2, xsa, wb1 + W_Q(l), wb2 + W_Q(l), sbw + SC_Q(l),
            bq + (size_t)l * CD, nullptr, q, M, CD, CD);
        tgemm<0><<<gDD, 256, TG_SMEM>>>(xa1, xa2, xsa, wb1 + W_K(l), wb2 + W_K(l), sbw + SC_K(l),
            bk + (size_t)l * CD, nullptr, k, M, CD, CD);
        tgemm<0><<<gDD, 256, TG_SMEM>>>(xa1, xa2, xsa, wb1 + W_V(l), wb2 + W_V(l), sbw + SC_V(l),
            bv + (size_t)l * CD, nullptr, v, M, CD, CD);

        rope_phi_kernel<<<(CB * CT * CH * 32 + 255) / 256, 256>>>(q, k);
        kv_partial<<<dim3(CB * CH, 8), 256>>>(k, v, kvp, ksp);
        kv_reduce<<<(CB * CH * CDH * CDH + CB * CH * CDH + 255) / 256, 256>>>(kvp, ksp, kv, ksum);
        attn_kernel<<<dim3(CB * CH, 8), 256>>>(q, kv, ksum, q);
        quant_rows<<<CM, 256>>>(q, qa1, qa2, qsa, CD);

        tgemm<0><<<gDD, 256, TG_SMEM>>>(qa1, qa2, qsa, wb1 + W_O(l), wb2 + W_O(l), sbw + SC_O(l),
            bo + (size_t)l * CD, nullptr, tmp, M, CD, CD);
        ln_quant<<<M, 256>>>(x, tmp, ln1g + (size_t)l * CD, ln1b + (size_t)l * CD, xa1, xa2, xsa);

        tgemm<1><<<gDF, 256, TG_SMEM>>>(xa1, xa2, xsa, wb1 + W_W1(l), wb2 + W_W1(l), sbw + SC_W1(l),
            b1 + (size_t)l * CFF, nullptr, ff, M, CFF, CD);
        quant_rows<<<CM, 256>>>(ff, fa1, fa2, fsa, CFF);
        tgemm<0><<<gDD, 256, TG_SMEM>>>(fa1, fa2, fsa, wb1 + W_W2(l), wb2 + W_W2(l), sbw + SC_W2(l),
            b2 + (size_t)l * CD, nullptr, tmp, M, CD, CFF);
        ln_quant<<<M, 256>>>(x, tmp, ln2g + (size_t)l * CD, ln2b + (size_t)l * CD, xa1, xa2, xsa);
    }

    ln_cls_kernel<<<CB, 256>>>(x, gN, bN, clsb);
    out_kernel<<<CV / 256, 256>>>(clsb, Wout, bout, out);
}